// round 15
// baseline (speedup 1.0000x reference)
#include <cuda_runtime.h>
#include <cuda_bf16.h>
#include <cstdint>

#define NODES_D 128
#define NMAX 50048        // padded to multiple of 128
#define EMAX 800000
#define WROWS 640         // packed rows: W1l,W1r,W2l,W2r (128 ea) + W3l,W3r (64 ea)

// Scratch (no allocations allowed)
__device__ float g_h1[NMAX * NODES_D];          // layer-1 activations fp32
__device__ float g_yl3[NMAX * 64];
__device__ float g_yr3[NMAX * 64];
__device__ __nv_bfloat16 g_xs_hi[NMAX * NODES_D];   // split x
__device__ __nv_bfloat16 g_xs_lo[NMAX * NODES_D];
__device__ __nv_bfloat16 g_agg_hi[NMAX * NODES_D];  // split gather output
__device__ __nv_bfloat16 g_agg_lo[NMAX * NODES_D];
__device__ __nv_bfloat16 g_h1_hi[NMAX * NODES_D];   // split h1
__device__ __nv_bfloat16 g_h1_lo[NMAX * NODES_D];
__device__ __nv_bfloat16 g_h2_hi[NMAX * NODES_D];   // split h2
__device__ __nv_bfloat16 g_h2_lo[NMAX * NODES_D];
__device__ __nv_bfloat16 g_whi[WROWS * NODES_D];
__device__ __nv_bfloat16 g_wlo[WROWS * NODES_D];
__device__ int   g_cnti[NMAX];
__device__ int   g_rp[NMAX + 1];    // block-local prefix (finalized on the fly)
__device__ int   g_rank[EMAX];
__device__ int2  g_ep[EMAX];
__device__ int   g_bsum[64];        // after scan2t: exclusive prefix of block sums

// ===========================================================================
// helpers
// ===========================================================================
__device__ __forceinline__ uint32_t smem_u32(const void* p) {
    uint32_t a;
    asm("{ .reg .u64 t; cvta.to.shared.u64 t, %1; cvt.u32.u64 %0, t; }"
        : "=r"(a) : "l"(p));
    return a;
}

__device__ __forceinline__ void ldm_x4(uint32_t* r, uint32_t addr) {
    asm volatile("ldmatrix.sync.aligned.m8n8.x4.shared.b16 {%0,%1,%2,%3}, [%4];"
                 : "=r"(r[0]), "=r"(r[1]), "=r"(r[2]), "=r"(r[3]) : "r"(addr));
}

__device__ __forceinline__ void mma_bf16(float* d, const uint32_t* a,
                                         const uint32_t* b) {
    asm volatile(
        "mma.sync.aligned.m16n8k16.row.col.f32.bf16.bf16.f32 "
        "{%0,%1,%2,%3}, {%4,%5,%6,%7}, {%8,%9}, {%0,%1,%2,%3};"
        : "+f"(d[0]), "+f"(d[1]), "+f"(d[2]), "+f"(d[3])
        : "r"(a[0]), "r"(a[1]), "r"(a[2]), "r"(a[3]), "r"(b[0]), "r"(b[1]));
}

__device__ __forceinline__ uint32_t pack2(__nv_bfloat16 a, __nv_bfloat16 b) {
    return (uint32_t)__bfloat16_as_ushort(a) |
           ((uint32_t)__bfloat16_as_ushort(b) << 16);
}

__device__ __forceinline__ void split4(float4 v, uint2& hp, uint2& lp) {
    __nv_bfloat16 hx = __float2bfloat16(v.x);
    __nv_bfloat16 hy = __float2bfloat16(v.y);
    __nv_bfloat16 hz = __float2bfloat16(v.z);
    __nv_bfloat16 hw = __float2bfloat16(v.w);
    hp = make_uint2(pack2(hx, hy), pack2(hz, hw));
    lp = make_uint2(
        pack2(__float2bfloat16(v.x - __bfloat162float(hx)),
              __float2bfloat16(v.y - __bfloat162float(hy))),
        pack2(__float2bfloat16(v.z - __bfloat162float(hz)),
              __float2bfloat16(v.w - __bfloat162float(hw))));
}

__device__ __forceinline__ void split2_store(__nv_bfloat16* oh, __nv_bfloat16* ol,
                                             size_t off, float f0, float f1) {
    __nv_bfloat16 h0 = __float2bfloat16(f0), h1 = __float2bfloat16(f1);
    __nv_bfloat16 l0 = __float2bfloat16(f0 - __bfloat162float(h0));
    __nv_bfloat16 l1 = __float2bfloat16(f1 - __bfloat162float(h1));
    *(uint32_t*)(oh + off) = pack2(h0, h1);
    *(uint32_t*)(ol + off) = pack2(l0, l1);
}

// cp.async helpers
__device__ __forceinline__ void cp16(uint32_t dst, const void* src) {
    asm volatile("cp.async.cg.shared.global [%0], [%1], 16;" :: "r"(dst), "l"(src));
}
__device__ __forceinline__ void cp_commit() {
    asm volatile("cp.async.commit_group;");
}
__device__ __forceinline__ void cp_wait_all() {
    asm volatile("cp.async.wait_group 0;");
}

// ===========================================================================
// fused prep kernel:
//   blocks [0, spb)        : split weights (rows 0..639) + x (rows 640..)
//   blocks [spb, spb+eb2)  : count dst degrees + record edge ranks (2/thread)
// ===========================================================================
__global__ void prep_k(const float* __restrict__ W1l, const float* __restrict__ W1r,
                       const float* __restrict__ W2l, const float* __restrict__ W2r,
                       const float* __restrict__ W3l, const float* __restrict__ W3r,
                       const float* __restrict__ x,
                       __nv_bfloat16* __restrict__ whi, __nv_bfloat16* __restrict__ wlo,
                       __nv_bfloat16* __restrict__ xh, __nv_bfloat16* __restrict__ xl,
                       const int* __restrict__ dst, int* __restrict__ cnti,
                       int* __restrict__ rank, int n, int E, int spb) {
    if (blockIdx.x < spb) {
        const int idx = blockIdx.x * blockDim.x + threadIdx.x;
        const int total = (WROWS + n) * 32;
        if (idx >= total) return;
        const int r = idx >> 5;
        const int c = (idx & 31) * 4;
        const float* srcp;
        __nv_bfloat16 *oh, *ol;
        size_t ooff;
        if (r < WROWS) {
            if      (r < 128) srcp = W1l + (size_t)r * 128;
            else if (r < 256) srcp = W1r + (size_t)(r - 128) * 128;
            else if (r < 384) srcp = W2l + (size_t)(r - 256) * 128;
            else if (r < 512) srcp = W2r + (size_t)(r - 384) * 128;
            else if (r < 576) srcp = W3l + (size_t)(r - 512) * 128;
            else              srcp = W3r + (size_t)(r - 576) * 128;
            oh = whi; ol = wlo;
            ooff = (size_t)r * 128 + c;
        } else {
            const int xr = r - WROWS;
            srcp = x + (size_t)xr * 128;
            oh = xh; ol = xl;
            ooff = (size_t)xr * 128 + c;
        }
        float4 v = *(const float4*)(srcp + c);
        uint2 hp, lp;
        split4(v, hp, lp);
        *(uint2*)(oh + ooff) = hp;
        *(uint2*)(ol + ooff) = lp;
    } else {
        const int base = (blockIdx.x - spb) * 512 + threadIdx.x;
#pragma unroll
        for (int i = 0; i < 2; ++i) {
            const int e = base + i * 256;
            if (e < E) rank[e] = atomicAdd(&cnti[dst[e]], 1);
        }
    }
}

// ===========================================================================
// CSR scans (rp stays block-local; bsum prefixed by scan2t; consumers
// finalize on the fly via rp[i] + bsum[i>>10])
// ===========================================================================
__global__ void scan1_k(const int* __restrict__ cnt, int* __restrict__ rp,
                        int* __restrict__ bsum, int n) {
    __shared__ int ws[8];
    const int tid = threadIdx.x, lane = tid & 31, wid = tid >> 5;
    const int i0 = blockIdx.x * 1024 + tid * 4;
    int v0 = (i0 + 0 < n) ? cnt[i0 + 0] : 0;
    int v1 = (i0 + 1 < n) ? cnt[i0 + 1] : 0;
    int v2 = (i0 + 2 < n) ? cnt[i0 + 2] : 0;
    int v3 = (i0 + 3 < n) ? cnt[i0 + 3] : 0;
    const int t = v0 + v1 + v2 + v3;
    int p = t;
#pragma unroll
    for (int o = 1; o < 32; o <<= 1) {
        int y = __shfl_up_sync(0xffffffffu, p, o);
        if (lane >= o) p += y;
    }
    if (lane == 31) ws[wid] = p;
    __syncthreads();
    if (wid == 0) {
        int w = (lane < 8) ? ws[lane] : 0;
        int pi = w;
#pragma unroll
        for (int o = 1; o < 8; o <<= 1) {
            int y = __shfl_up_sync(0xffffffffu, pi, o);
            if (lane >= o) pi += y;
        }
        if (lane == 7) bsum[blockIdx.x] = pi;
        if (lane < 8) ws[lane] = pi - w;
    }
    __syncthreads();
    const int off = ws[wid] + (p - t);
    if (i0 + 0 < n) rp[i0 + 0] = off;
    if (i0 + 1 < n) rp[i0 + 1] = off + v0;
    if (i0 + 2 < n) rp[i0 + 2] = off + v0 + v1;
    if (i0 + 3 < n) rp[i0 + 3] = off + v0 + v1 + v2;
}

// tiny exclusive prefix of block sums (nb <= 64), in place
__global__ void scan2t_k(int* __restrict__ bsum, int nb) {
    __shared__ int w0s;
    const int tid = threadIdx.x;         // 64 threads
    const int lane = tid & 31, wid = tid >> 5;
    int v = (tid < nb) ? bsum[tid] : 0;
    int p = v;
#pragma unroll
    for (int o = 1; o < 32; o <<= 1) {
        int y = __shfl_up_sync(0xffffffffu, p, o);
        if (lane >= o) p += y;
    }
    if (wid == 0 && lane == 31) w0s = p;
    __syncthreads();
    bsum[tid] = p - v + (wid ? w0s : 0);
}

// atomic-free fill (2 edges/thread), finalizes rp on the fly
__global__ void fill_k(const int* __restrict__ src, const int* __restrict__ dst,
                       const float* __restrict__ ew, const int* __restrict__ rp,
                       const int* __restrict__ bsum, const int* __restrict__ rank,
                       int2* __restrict__ ep, int E) {
    __shared__ int sb[64];
    if (threadIdx.x < 64) sb[threadIdx.x] = bsum[threadIdx.x];
    __syncthreads();
    const int base = blockIdx.x * 512 + threadIdx.x;
#pragma unroll
    for (int i = 0; i < 2; ++i) {
        const int e = base + i * 256;
        if (e < E) {
            const int d = dst[e];
            const int p = rp[d] + sb[d >> 10] + rank[e];
            ep[p] = make_int2(src[e], __float_as_int(ew[e]));
        }
    }
}

// ===========================================================================
// Pull aggregation: mean of w*x[src], 128-wide fp32 in, writes SPLIT planes
// ===========================================================================
__global__ void __launch_bounds__(256)
gather_sp(const float* __restrict__ x, const int* __restrict__ rp,
          const int* __restrict__ bsum, const int2* __restrict__ ep,
          __nv_bfloat16* __restrict__ aggh, __nv_bfloat16* __restrict__ aggl,
          int n, int E) {
    __shared__ int sb[64];
    if (threadIdx.x < 64) sb[threadIdx.x] = bsum[threadIdx.x];
    __syncthreads();

    const int node = (blockIdx.x * blockDim.x + threadIdx.x) >> 5;
    const int lane = threadIdx.x & 31;
    if (node >= n) return;

    const int s0 = rp[node] + sb[node >> 10];
    const int nn = node + 1;
    const int s1 = (nn == n) ? E : rp[nn] + sb[nn >> 10];
    const float* xb = x + lane * 4;

    float ax = 0.f, ay = 0.f, az = 0.f, aw = 0.f;
    for (int base = s0; base < s1; base += 32) {
        const int m = min(32, s1 - base);
        int2 meta = make_int2(0, 0);
        if (lane < m) meta = ep[base + lane];
        int t = 0;
        for (; t + 4 <= m; t += 4) {
            const int   sA = __shfl_sync(0xffffffffu, meta.x, t);
            const float wA = __int_as_float(__shfl_sync(0xffffffffu, meta.y, t));
            const int   sB = __shfl_sync(0xffffffffu, meta.x, t + 1);
            const float wB = __int_as_float(__shfl_sync(0xffffffffu, meta.y, t + 1));
            const int   sC = __shfl_sync(0xffffffffu, meta.x, t + 2);
            const float wC = __int_as_float(__shfl_sync(0xffffffffu, meta.y, t + 2));
            const int   sD = __shfl_sync(0xffffffffu, meta.x, t + 3);
            const float wD = __int_as_float(__shfl_sync(0xffffffffu, meta.y, t + 3));
            const float4 vA = *(const float4*)(xb + (size_t)sA * NODES_D);
            const float4 vB = *(const float4*)(xb + (size_t)sB * NODES_D);
            const float4 vC = *(const float4*)(xb + (size_t)sC * NODES_D);
            const float4 vD = *(const float4*)(xb + (size_t)sD * NODES_D);
            ax += vA.x * wA + vB.x * wB + vC.x * wC + vD.x * wD;
            ay += vA.y * wA + vB.y * wB + vC.y * wC + vD.y * wD;
            az += vA.z * wA + vB.z * wB + vC.z * wC + vD.z * wD;
            aw += vA.w * wA + vB.w * wB + vC.w * wC + vD.w * wD;
        }
        for (; t < m; ++t) {
            const int   sA = __shfl_sync(0xffffffffu, meta.x, t);
            const float wA = __int_as_float(__shfl_sync(0xffffffffu, meta.y, t));
            const float4 vA = *(const float4*)(xb + (size_t)sA * NODES_D);
            ax += vA.x * wA; ay += vA.y * wA; az += vA.z * wA; aw += vA.w * wA;
        }
    }
    const float inv = 1.0f / fmaxf((float)(s1 - s0), 1.0f);
    float4 mv = make_float4(ax * inv, ay * inv, az * inv, aw * inv);
    uint2 hp, lp;
    split4(mv, hp, lp);
    const size_t off = (size_t)node * NODES_D + lane * 4;
    *(uint2*)(aggh + off) = hp;
    *(uint2*)(aggl + off) = lp;
}

// ===========================================================================
// Pipelined HMMA GEMM. 128x128 tile, 8 warps (4x2), K = NC*32.
// All inputs pre-split bf16 hi/lo in global -> pure cp.async staging,
// 2-stage double buffer. Chunks 0-3 read (a0h,a0l), 4-7 read (a1h,a1l).
// EPI: 0 = BN+leaky -> fp32 out + hi/lo planes (layer 1)
//      1 = BN+leaky -> hi/lo planes only       (layer 2)
//      2 = +bias upper half -> yl/yr fp32 64-wide (layer 3 transform)
// ===========================================================================
#define STRIDE 80
#define PSZ (128 * STRIDE)
#define BUFSZ (4 * PSZ)
#define OFF_MUL (2 * BUFSZ)
#define OFF_ADD (OFF_MUL + 128 * 4)
#define SMEM_PIPE (OFF_ADD + 128 * 4)

template <int NC, int EPI>
__global__ void __launch_bounds__(256)
gemm_pipe(const __nv_bfloat16* __restrict__ a0h, const __nv_bfloat16* __restrict__ a0l,
          const __nv_bfloat16* __restrict__ a1h, const __nv_bfloat16* __restrict__ a1l,
          const __nv_bfloat16* __restrict__ whi, const __nv_bfloat16* __restrict__ wlo,
          int wbase, const float* __restrict__ bias,
          const float* __restrict__ bng, const float* __restrict__ bnb,
          const float* __restrict__ bnm, const float* __restrict__ bnv,
          float* __restrict__ out, __nv_bfloat16* __restrict__ oh,
          __nv_bfloat16* __restrict__ ol, float* __restrict__ outr, int n) {
    extern __shared__ char smem[];
    const uint32_t sbase = smem_u32(smem);
    float* s_mul = (float*)(smem + OFF_MUL);
    float* s_add = (float*)(smem + OFF_ADD);

    const int tid = threadIdx.x;
    const int wid = tid >> 5;
    const int lane = tid & 31;
    const int row0 = blockIdx.x * 128;

    if (tid < 128) {
        if (EPI == 2) {
            s_add[tid] = (tid >= 64) ? bias[tid - 64] : 0.f;
        } else {
            float s = bng[tid] * rsqrtf(bnv[tid] + 1e-5f);
            s_mul[tid] = s;
            s_add[tid] = (bias[tid] - bnm[tid]) * s + bnb[tid];
        }
    }

    const int mrow0 = (wid & 3) * 32;
    const int ncol0 = (wid >> 2) * 64;

    const int sel = lane >> 3;
    const int lr8 = lane & 7;
    uint32_t aOff[2], bOff[4];
#pragma unroll
    for (int m = 0; m < 2; ++m)
        aOff[m] = (uint32_t)((mrow0 + m * 16 + (sel & 1) * 8 + lr8) * STRIDE +
                             (sel >> 1) * 16);
#pragma unroll
    for (int g = 0; g < 4; ++g)
        bOff[g] = (uint32_t)((ncol0 + g * 16 + (sel >> 1) * 8 + lr8) * STRIDE +
                             (sel & 1) * 16);

    auto load_chunk = [&](int buf, int ch) {
        const __nv_bfloat16* ah = (ch < 4) ? a0h : a1h;
        const __nv_bfloat16* al = (ch < 4) ? a0l : a1l;
        const int col0 = (ch & 3) * 32;
        const int wrow = wbase + ((ch < 4) ? 0 : 128);
        const uint32_t base = sbase + buf * BUFSZ;
#pragma unroll
        for (int i = 0; i < 2; ++i) {
            const int idx = tid + i * 256;
            const int r = idx >> 2;
            const uint32_t soff = (uint32_t)(r * STRIDE + (idx & 3) * 16);
            const int ge = col0 + (idx & 3) * 8;
            const size_t aoff = (size_t)(row0 + r) * 128 + ge;
            cp16(base + soff, ah + aoff);
            cp16(base + PSZ + soff, al + aoff);
            const size_t woff2 = (size_t)(wrow + r) * 128 + ge;
            cp16(base + 2 * PSZ + soff, whi + woff2);
            cp16(base + 3 * PSZ + soff, wlo + woff2);
        }
    };

    float acc[2][8][4];
#pragma unroll
    for (int m = 0; m < 2; ++m)
#pragma unroll
        for (int g = 0; g < 8; ++g)
#pragma unroll
            for (int q = 0; q < 4; ++q) acc[m][g][q] = 0.f;

    load_chunk(0, 0);
    cp_commit();

    for (int ch = 0; ch < NC; ++ch) {
        const int cur = ch & 1;
        cp_wait_all();
        __syncthreads();
        if (ch + 1 < NC) {
            load_chunk(cur ^ 1, ch + 1);
            cp_commit();
        }
        const uint32_t b0 = sbase + cur * BUFSZ;
#pragma unroll
        for (int kk = 0; kk < 2; ++kk) {
            const uint32_t kb = kk * 32;
            uint32_t ah[2][4], al[2][4];
            ldm_x4(ah[0], b0 + aOff[0] + kb);
            ldm_x4(al[0], b0 + PSZ + aOff[0] + kb);
            ldm_x4(ah[1], b0 + aOff[1] + kb);
            ldm_x4(al[1], b0 + PSZ + aOff[1] + kb);
#pragma unroll
            for (int g = 0; g < 4; ++g) {
                uint32_t bh[4], bl[4];
                ldm_x4(bh, b0 + 2 * PSZ + bOff[g] + kb);
                ldm_x4(bl, b0 + 3 * PSZ + bOff[g] + kb);
#pragma unroll
                for (int m = 0; m < 2; ++m) {
                    mma_bf16(acc[m][g * 2],     ah[m], bh);
                    mma_bf16(acc[m][g * 2],     al[m], bh);
                    mma_bf16(acc[m][g * 2],     ah[m], bl);
                    mma_bf16(acc[m][g * 2 + 1], ah[m], bh + 2);
                    mma_bf16(acc[m][g * 2 + 1], al[m], bh + 2);
                    mma_bf16(acc[m][g * 2 + 1], ah[m], bl + 2);
                }
            }
        }
        __syncthreads();
    }

    // ---- epilogue ----
    const int qrow = lane >> 2;
    const int qcol = (lane & 3) * 2;
#pragma unroll
    for (int m = 0; m < 2; ++m) {
        const int rA = row0 + mrow0 + m * 16 + qrow;
        const int rB = rA + 8;
#pragma unroll
        for (int g = 0; g < 8; ++g) {
            const int c0 = ncol0 + g * 8 + qcol;
            if (EPI == 2) {
                const bool is_yr = (c0 >= 64);
                float* outp = is_yr ? outr : out;
                const int cl = c0 - (is_yr ? 64 : 0);
                const float a0 = s_add[c0], a1 = s_add[c0 + 1];
                if (rA < n) {
                    float2 o;
                    o.x = acc[m][g][0] + a0;
                    o.y = acc[m][g][1] + a1;
                    *(float2*)(outp + (size_t)rA * 64 + cl) = o;
                }
                if (rB < n) {
                    float2 o;
                    o.x = acc[m][g][2] + a0;
                    o.y = acc[m][g][3] + a1;
                    *(float2*)(outp + (size_t)rB * 64 + cl) = o;
                }
            } else {
                const float m0 = s_mul[c0], m1 = s_mul[c0 + 1];
                const float a0 = s_add[c0], a1 = s_add[c0 + 1];
                if (rA < n) {
                    float f0 = acc[m][g][0] * m0 + a0;
                    float f1 = acc[m][g][1] * m1 + a1;
                    f0 = (f0 >= 0.f) ? f0 : 0.1f * f0;
                    f1 = (f1 >= 0.f) ? f1 : 0.1f * f1;
                    const size_t off = (size_t)rA * 128 + c0;
                    if (EPI == 0) {
                        float2 o; o.x = f0; o.y = f1;
                        *(float2*)(out + off) = o;
                    }
                    split2_store(oh, ol, off, f0, f1);
                }
                if (rB < n) {
                    float f2 = acc[m][g][2] * m0 + a0;
                    float f3 = acc[m][g][3] * m1 + a1;
                    f2 = (f2 >= 0.f) ? f2 : 0.1f * f2;
                    f3 = (f3 >= 0.f) ? f3 : 0.1f * f3;
                    const size_t off = (size_t)rB * 128 + c0;
                    if (EPI == 0) {
                        float2 o; o.x = f2; o.y = f3;
                        *(float2*)(out + off) = o;
                    }
                    split2_store(oh, ol, off, f2, f3);
                }
            }
        }
    }
}

// ===========================================================================
// gather+normalize (layer 3): out = l2norm(mean(w*yl3[src]) + yr3[node]), D=64
// ===========================================================================
__global__ void __launch_bounds__(256)
gather_fin(const float* __restrict__ yl, const float* __restrict__ yr,
           const int* __restrict__ rp, const int* __restrict__ bsum,
           const int2* __restrict__ ep, float* __restrict__ out, int n, int E) {
    __shared__ int sb[64];
    if (threadIdx.x < 64) sb[threadIdx.x] = bsum[threadIdx.x];
    __syncthreads();

    const int node = (blockIdx.x * blockDim.x + threadIdx.x) >> 5;
    const int lane = threadIdx.x & 31;
    if (node >= n) return;

    const int s0 = rp[node] + sb[node >> 10];
    const int nn = node + 1;
    const int s1 = (nn == n) ? E : rp[nn] + sb[nn >> 10];
    const float* xb = yl + lane * 2;

    float ax = 0.f, ay = 0.f;
    for (int base = s0; base < s1; base += 32) {
        const int m = min(32, s1 - base);
        int2 meta = make_int2(0, 0);
        if (lane < m) meta = ep[base + lane];
        int t = 0;
        for (; t + 4 <= m; t += 4) {
            const int   sA = __shfl_sync(0xffffffffu, meta.x, t);
            const float wA = __int_as_float(__shfl_sync(0xffffffffu, meta.y, t));
            const int   sB = __shfl_sync(0xffffffffu, meta.x, t + 1);
            const float wB = __int_as_float(__shfl_sync(0xffffffffu, meta.y, t + 1));
            const int   sC = __shfl_sync(0xffffffffu, meta.x, t + 2);
            const float wC = __int_as_float(__shfl_sync(0xffffffffu, meta.y, t + 2));
            const int   sD = __shfl_sync(0xffffffffu, meta.x, t + 3);
            const float wD = __int_as_float(__shfl_sync(0xffffffffu, meta.y, t + 3));
            const float2 vA = *(const float2*)(xb + (size_t)sA * 64);
            const float2 vB = *(const float2*)(xb + (size_t)sB * 64);
            const float2 vC = *(const float2*)(xb + (size_t)sC * 64);
            const float2 vD = *(const float2*)(xb + (size_t)sD * 64);
            ax += vA.x * wA + vB.x * wB + vC.x * wC + vD.x * wD;
            ay += vA.y * wA + vB.y * wB + vC.y * wC + vD.y * wD;
        }
        for (; t < m; ++t) {
            const int   sA = __shfl_sync(0xffffffffu, meta.x, t);
            const float wA = __int_as_float(__shfl_sync(0xffffffffu, meta.y, t));
            const float2 vA = *(const float2*)(xb + (size_t)sA * 64);
            ax += vA.x * wA; ay += vA.y * wA;
        }
    }
    const float inv = 1.0f / fmaxf((float)(s1 - s0), 1.0f);
    const float2 r = *(const float2*)(yr + (size_t)node * 64 + lane * 2);
    float v0 = ax * inv + r.x;
    float v1 = ay * inv + r.y;
    float ss = v0 * v0 + v1 * v1;
#pragma unroll
    for (int o = 16; o; o >>= 1) ss += __shfl_xor_sync(0xffffffffu, ss, o);
    const float sc = 1.0f / fmaxf(sqrtf(ss), 1e-12f);
    float2 o;
    o.x = v0 * sc; o.y = v1 * sc;
    *(float2*)(out + (size_t)node * 64 + lane * 2) = o;
}

// ===========================================================================
extern "C" void kernel_launch(void* const* d_in, const int* in_sizes, int n_in,
                              void* d_out, int out_size) {
    const float* x    = (const float*)d_in[0];
    const int*   ei   = (const int*)d_in[1];   // int32 (JAX canonicalizes int64)
    const float* ew   = (const float*)d_in[2];
    const float* W1l  = (const float*)d_in[3];
    const float* b1   = (const float*)d_in[4];
    const float* W1r  = (const float*)d_in[5];
    const float* W2l  = (const float*)d_in[6];
    const float* b2   = (const float*)d_in[7];
    const float* W2r  = (const float*)d_in[8];
    const float* W3l  = (const float*)d_in[9];
    const float* b3   = (const float*)d_in[10];
    const float* W3r  = (const float*)d_in[11];
    const float* bn1g = (const float*)d_in[12];
    const float* bn1b = (const float*)d_in[13];
    const float* bn1m = (const float*)d_in[14];
    const float* bn1v = (const float*)d_in[15];
    const float* bn2g = (const float*)d_in[16];
    const float* bn2b = (const float*)d_in[17];
    const float* bn2m = (const float*)d_in[18];
    const float* bn2v = (const float*)d_in[19];

    const int n = in_sizes[0] / NODES_D;
    const int e = in_sizes[2];

    float *h1, *yl3, *yr3;
    int *cnti, *rp, *rankp, *bsum;
    int2 *ep;
    __nv_bfloat16 *xsh, *xsl, *aggh, *aggl, *h1h, *h1l, *h2h, *h2l, *whi, *wlo;
    cudaGetSymbolAddress((void**)&h1, g_h1);
    cudaGetSymbolAddress((void**)&yl3, g_yl3);
    cudaGetSymbolAddress((void**)&yr3, g_yr3);
    cudaGetSymbolAddress((void**)&xsh, g_xs_hi);
    cudaGetSymbolAddress((void**)&xsl, g_xs_lo);
    cudaGetSymbolAddress((void**)&aggh, g_agg_hi);
    cudaGetSymbolAddress((void**)&aggl, g_agg_lo);
    cudaGetSymbolAddress((void**)&h1h, g_h1_hi);
    cudaGetSymbolAddress((void**)&h1l, g_h1_lo);
    cudaGetSymbolAddress((void**)&h2h, g_h2_hi);
    cudaGetSymbolAddress((void**)&h2l, g_h2_lo);
    cudaGetSymbolAddress((void**)&whi, g_whi);
    cudaGetSymbolAddress((void**)&wlo, g_wlo);
    cudaGetSymbolAddress((void**)&cnti, g_cnti);
    cudaGetSymbolAddress((void**)&rp, g_rp);
    cudaGetSymbolAddress((void**)&rankp, g_rank);
    cudaGetSymbolAddress((void**)&bsum, g_bsum);
    cudaGetSymbolAddress((void**)&ep, g_ep);

    cudaFuncSetAttribute(gemm_pipe<8, 0>,
                         cudaFuncAttributeMaxDynamicSharedMemorySize, SMEM_PIPE);
    cudaFuncSetAttribute(gemm_pipe<8, 1>,
                         cudaFuncAttributeMaxDynamicSharedMemorySize, SMEM_PIPE);
    cudaFuncSetAttribute(gemm_pipe<4, 2>,
                         cudaFuncAttributeMaxDynamicSharedMemorySize, SMEM_PIPE);

    const int* src = ei;
    const int* dst = ei + e;

    const int eb2 = (e + 511) / 512;
    const int nb1024 = (n + 1023) / 1024;
    const int spb = ((WROWS + n) * 32 + 255) / 256;
    const int gbk = (n + 7) / 8;            // gather: 8 warps/block
    const int gb  = (n + 127) / 128;        // gemm: 128 rows/block

    // ---- prep (splits + degree count) + CSR ----
    cudaMemsetAsync(cnti, 0, (size_t)n * sizeof(int), 0);
    prep_k<<<spb + eb2, 256>>>(W1l, W1r, W2l, W2r, W3l, W3r, x,
                               whi, wlo, xsh, xsl, dst, cnti, rankp, n, e, spb);
    scan1_k<<<nb1024, 256>>>(cnti, rp, bsum, n);
    scan2t_k<<<1, 64>>>(bsum, nb1024);
    fill_k<<<eb2, 256>>>(src, dst, ew, rp, bsum, rankp, ep, e);

    // ---- Layer 1 ----
    gather_sp<<<gbk, 256>>>(x, rp, bsum, ep, aggh, aggl, n, e);
    gemm_pipe<8, 0><<<gb, 256, SMEM_PIPE>>>(aggh, aggl, xsh, xsl, whi, wlo, 0,
                                            b1, bn1g, bn1b, bn1m, bn1v,
                                            h1, h1h, h1l, nullptr, n);
    // ---- Layer 2 ----
    gather_sp<<<gbk, 256>>>(h1, rp, bsum, ep, aggh, aggl, n, e);
    gemm_pipe<8, 1><<<gb, 256, SMEM_PIPE>>>(aggh, aggl, h1h, h1l, whi, wlo, 256,
                                            b2, bn2g, bn2b, bn2m, bn2v,
                                            nullptr, h2h, h2l, nullptr, n);
    // ---- Layer 3 (transform-first + L2 normalize) ----
    gemm_pipe<4, 2><<<gb, 256, SMEM_PIPE>>>(h2h, h2l, nullptr, nullptr, whi, wlo, 512,
                                            b3, nullptr, nullptr, nullptr, nullptr,
                                            yl3, nullptr, nullptr, yr3, n);
    gather_fin<<<gbk, 256>>>(yl3, yr3, rp, bsum, ep, (float*)d_out, n, e);
}

// round 16
// speedup vs baseline: 1.0163x; 1.0163x over previous
#include <cuda_runtime.h>
#include <cuda_bf16.h>
#include <cstdint>

#define NODES_D 128
#define NMAX 50048        // padded to multiple of 128
#define EMAX 800000
#define WROWS 640         // packed rows: W1l,W1r,W2l,W2r (128 ea) + W3l,W3r (64 ea)

// Scratch (no allocations allowed)
__device__ float g_h1[NMAX * NODES_D];          // layer-1 activations fp32
__device__ float g_yl3[NMAX * 64];
__device__ float g_yr3[NMAX * 64];
__device__ __nv_bfloat16 g_xs_hi[NMAX * NODES_D];   // split x
__device__ __nv_bfloat16 g_xs_lo[NMAX * NODES_D];
__device__ __nv_bfloat16 g_agg_hi[NMAX * NODES_D];  // split gather output
__device__ __nv_bfloat16 g_agg_lo[NMAX * NODES_D];
__device__ __nv_bfloat16 g_h1_hi[NMAX * NODES_D];   // split h1
__device__ __nv_bfloat16 g_h1_lo[NMAX * NODES_D];
__device__ __nv_bfloat16 g_h2_hi[NMAX * NODES_D];   // split h2
__device__ __nv_bfloat16 g_h2_lo[NMAX * NODES_D];
__device__ __nv_bfloat16 g_whi[WROWS * NODES_D];
__device__ __nv_bfloat16 g_wlo[WROWS * NODES_D];
__device__ int   g_cnti[NMAX];
__device__ int   g_rp[NMAX + 1];
__device__ int   g_rank[EMAX];
__device__ int2  g_ep[EMAX];
__device__ int   g_bsum[64];

// ===========================================================================
// helpers
// ===========================================================================
__device__ __forceinline__ uint32_t smem_u32(const void* p) {
    uint32_t a;
    asm("{ .reg .u64 t; cvta.to.shared.u64 t, %1; cvt.u32.u64 %0, t; }"
        : "=r"(a) : "l"(p));
    return a;
}

__device__ __forceinline__ void ldm_x4(uint32_t* r, uint32_t addr) {
    asm volatile("ldmatrix.sync.aligned.m8n8.x4.shared.b16 {%0,%1,%2,%3}, [%4];"
                 : "=r"(r[0]), "=r"(r[1]), "=r"(r[2]), "=r"(r[3]) : "r"(addr));
}

__device__ __forceinline__ void mma_bf16(float* d, const uint32_t* a,
                                         const uint32_t* b) {
    asm volatile(
        "mma.sync.aligned.m16n8k16.row.col.f32.bf16.bf16.f32 "
        "{%0,%1,%2,%3}, {%4,%5,%6,%7}, {%8,%9}, {%0,%1,%2,%3};"
        : "+f"(d[0]), "+f"(d[1]), "+f"(d[2]), "+f"(d[3])
        : "r"(a[0]), "r"(a[1]), "r"(a[2]), "r"(a[3]), "r"(b[0]), "r"(b[1]));
}

__device__ __forceinline__ uint32_t pack2(__nv_bfloat16 a, __nv_bfloat16 b) {
    return (uint32_t)__bfloat16_as_ushort(a) |
           ((uint32_t)__bfloat16_as_ushort(b) << 16);
}

__device__ __forceinline__ void split4(float4 v, uint2& hp, uint2& lp) {
    __nv_bfloat16 hx = __float2bfloat16(v.x);
    __nv_bfloat16 hy = __float2bfloat16(v.y);
    __nv_bfloat16 hz = __float2bfloat16(v.z);
    __nv_bfloat16 hw = __float2bfloat16(v.w);
    hp = make_uint2(pack2(hx, hy), pack2(hz, hw));
    lp = make_uint2(
        pack2(__float2bfloat16(v.x - __bfloat162float(hx)),
              __float2bfloat16(v.y - __bfloat162float(hy))),
        pack2(__float2bfloat16(v.z - __bfloat162float(hz)),
              __float2bfloat16(v.w - __bfloat162float(hw))));
}

__device__ __forceinline__ void split2_store(__nv_bfloat16* oh, __nv_bfloat16* ol,
                                             size_t off, float f0, float f1) {
    __nv_bfloat16 h0 = __float2bfloat16(f0), h1 = __float2bfloat16(f1);
    __nv_bfloat16 l0 = __float2bfloat16(f0 - __bfloat162float(h0));
    __nv_bfloat16 l1 = __float2bfloat16(f1 - __bfloat162float(h1));
    *(uint32_t*)(oh + off) = pack2(h0, h1);
    *(uint32_t*)(ol + off) = pack2(l0, l1);
}

// cp.async helpers
__device__ __forceinline__ void cp16(uint32_t dst, const void* src) {
    asm volatile("cp.async.cg.shared.global [%0], [%1], 16;" :: "r"(dst), "l"(src));
}
__device__ __forceinline__ void cp_commit() {
    asm volatile("cp.async.commit_group;");
}
__device__ __forceinline__ void cp_wait_all() {
    asm volatile("cp.async.wait_group 0;");
}

// ===========================================================================
// fused prep kernel:
//   blocks [0, spb)        : split weights (rows 0..639) + x (rows 640..)
//   blocks [spb, spb+eb)   : count dst degrees + record edge ranks
// ===========================================================================
__global__ void prep_k(const float* __restrict__ W1l, const float* __restrict__ W1r,
                       const float* __restrict__ W2l, const float* __restrict__ W2r,
                       const float* __restrict__ W3l, const float* __restrict__ W3r,
                       const float* __restrict__ x,
                       __nv_bfloat16* __restrict__ whi, __nv_bfloat16* __restrict__ wlo,
                       __nv_bfloat16* __restrict__ xh, __nv_bfloat16* __restrict__ xl,
                       const int* __restrict__ dst, int* __restrict__ cnti,
                       int* __restrict__ rank, int n, int E, int spb) {
    if (blockIdx.x < spb) {
        const int idx = blockIdx.x * blockDim.x + threadIdx.x;
        const int total = (WROWS + n) * 32;
        if (idx >= total) return;
        const int r = idx >> 5;
        const int c = (idx & 31) * 4;
        const float* srcp;
        __nv_bfloat16 *oh, *ol;
        size_t ooff;
        if (r < WROWS) {
            if      (r < 128) srcp = W1l + (size_t)r * 128;
            else if (r < 256) srcp = W1r + (size_t)(r - 128) * 128;
            else if (r < 384) srcp = W2l + (size_t)(r - 256) * 128;
            else if (r < 512) srcp = W2r + (size_t)(r - 384) * 128;
            else if (r < 576) srcp = W3l + (size_t)(r - 512) * 128;
            else              srcp = W3r + (size_t)(r - 576) * 128;
            oh = whi; ol = wlo;
            ooff = (size_t)r * 128 + c;
        } else {
            const int xr = r - WROWS;
            srcp = x + (size_t)xr * 128;
            oh = xh; ol = xl;
            ooff = (size_t)xr * 128 + c;
        }
        float4 v = *(const float4*)(srcp + c);
        uint2 hp, lp;
        split4(v, hp, lp);
        *(uint2*)(oh + ooff) = hp;
        *(uint2*)(ol + ooff) = lp;
    } else {
        const int e = (blockIdx.x - spb) * blockDim.x + threadIdx.x;
        if (e < E) rank[e] = atomicAdd(&cnti[dst[e]], 1);
    }
}

// ===========================================================================
// CSR scans + fill
// ===========================================================================
__global__ void scan1_k(const int* __restrict__ cnt, int* __restrict__ rp,
                        int* __restrict__ bsum, int n) {
    __shared__ int ws[8];
    const int tid = threadIdx.x, lane = tid & 31, wid = tid >> 5;
    const int i0 = blockIdx.x * 1024 + tid * 4;
    int v0 = (i0 + 0 < n) ? cnt[i0 + 0] : 0;
    int v1 = (i0 + 1 < n) ? cnt[i0 + 1] : 0;
    int v2 = (i0 + 2 < n) ? cnt[i0 + 2] : 0;
    int v3 = (i0 + 3 < n) ? cnt[i0 + 3] : 0;
    const int t = v0 + v1 + v2 + v3;
    int p = t;
#pragma unroll
    for (int o = 1; o < 32; o <<= 1) {
        int y = __shfl_up_sync(0xffffffffu, p, o);
        if (lane >= o) p += y;
    }
    if (lane == 31) ws[wid] = p;
    __syncthreads();
    if (wid == 0) {
        int w = (lane < 8) ? ws[lane] : 0;
        int pi = w;
#pragma unroll
        for (int o = 1; o < 8; o <<= 1) {
            int y = __shfl_up_sync(0xffffffffu, pi, o);
            if (lane >= o) pi += y;
        }
        if (lane == 7) bsum[blockIdx.x] = pi;
        if (lane < 8) ws[lane] = pi - w;
    }
    __syncthreads();
    const int off = ws[wid] + (p - t);
    if (i0 + 0 < n) rp[i0 + 0] = off;
    if (i0 + 1 < n) rp[i0 + 1] = off + v0;
    if (i0 + 2 < n) rp[i0 + 2] = off + v0 + v1;
    if (i0 + 3 < n) rp[i0 + 3] = off + v0 + v1 + v2;
}

__global__ void scan3m_k(int* __restrict__ rp, const int* __restrict__ bsum,
                         int n, int E, int nb) {
    __shared__ int sb[64];
    const int tid = threadIdx.x;
    if (tid < 64) sb[tid] = (tid < nb) ? bsum[tid] : 0;
    __syncthreads();
    if (tid == 0) {
        int run = 0;
#pragma unroll
        for (int i = 0; i < 64; ++i) { int t = sb[i]; sb[i] = run; run += t; }
    }
    __syncthreads();
    const int i = blockIdx.x * blockDim.x + tid;
    if (i < n) rp[i] += sb[i >> 10];
    if (i == 0) rp[n] = E;
}

__global__ void fill_k(const int* __restrict__ src, const int* __restrict__ dst,
                       const float* __restrict__ ew, const int* __restrict__ rp,
                       const int* __restrict__ rank, int2* __restrict__ ep, int E) {
    int e = blockIdx.x * blockDim.x + threadIdx.x;
    if (e < E) {
        int p = rp[dst[e]] + rank[e];
        ep[p] = make_int2(src[e], __float_as_int(ew[e]));
    }
}

// ===========================================================================
// Pull aggregation: mean of w*x[src], 128-wide fp32 in, writes SPLIT planes
// ===========================================================================
__global__ void __launch_bounds__(256)
gather_sp(const float* __restrict__ x, const int* __restrict__ rp,
          const int2* __restrict__ ep,
          __nv_bfloat16* __restrict__ aggh, __nv_bfloat16* __restrict__ aggl,
          int n) {
    const int node = (blockIdx.x * blockDim.x + threadIdx.x) >> 5;
    const int lane = threadIdx.x & 31;
    if (node >= n) return;

    const int s0 = rp[node];
    const int s1 = rp[node + 1];
    const float* xb = x + lane * 4;

    float ax = 0.f, ay = 0.f, az = 0.f, aw = 0.f;
    for (int base = s0; base < s1; base += 32) {
        const int m = min(32, s1 - base);
        int2 meta = make_int2(0, 0);
        if (lane < m) meta = ep[base + lane];
        int t = 0;
        for (; t + 4 <= m; t += 4) {
            const int   sA = __shfl_sync(0xffffffffu, meta.x, t);
            const float wA = __int_as_float(__shfl_sync(0xffffffffu, meta.y, t));
            const int   sB = __shfl_sync(0xffffffffu, meta.x, t + 1);
            const float wB = __int_as_float(__shfl_sync(0xffffffffu, meta.y, t + 1));
            const int   sC = __shfl_sync(0xffffffffu, meta.x, t + 2);
            const float wC = __int_as_float(__shfl_sync(0xffffffffu, meta.y, t + 2));
            const int   sD = __shfl_sync(0xffffffffu, meta.x, t + 3);
            const float wD = __int_as_float(__shfl_sync(0xffffffffu, meta.y, t + 3));
            const float4 vA = *(const float4*)(xb + (size_t)sA * NODES_D);
            const float4 vB = *(const float4*)(xb + (size_t)sB * NODES_D);
            const float4 vC = *(const float4*)(xb + (size_t)sC * NODES_D);
            const float4 vD = *(const float4*)(xb + (size_t)sD * NODES_D);
            ax += vA.x * wA + vB.x * wB + vC.x * wC + vD.x * wD;
            ay += vA.y * wA + vB.y * wB + vC.y * wC + vD.y * wD;
            az += vA.z * wA + vB.z * wB + vC.z * wC + vD.z * wD;
            aw += vA.w * wA + vB.w * wB + vC.w * wC + vD.w * wD;
        }
        for (; t < m; ++t) {
            const int   sA = __shfl_sync(0xffffffffu, meta.x, t);
            const float wA = __int_as_float(__shfl_sync(0xffffffffu, meta.y, t));
            const float4 vA = *(const float4*)(xb + (size_t)sA * NODES_D);
            ax += vA.x * wA; ay += vA.y * wA; az += vA.z * wA; aw += vA.w * wA;
        }
    }
    const float inv = 1.0f / fmaxf((float)(s1 - s0), 1.0f);
    float4 mv = make_float4(ax * inv, ay * inv, az * inv, aw * inv);
    uint2 hp, lp;
    split4(mv, hp, lp);
    const size_t off = (size_t)node * NODES_D + lane * 4;
    *(uint2*)(aggh + off) = hp;
    *(uint2*)(aggl + off) = lp;
}

// ===========================================================================
// Pipelined HMMA GEMM. 128x128 tile, 8 warps (4x2), K = NC*32.
// All inputs pre-split bf16 hi/lo in global -> pure cp.async staging,
// 2-stage double buffer. Chunks 0-3 read (a0h,a0l), 4-7 read (a1h,a1l).
// EPI: 0 = BN+leaky -> fp32 out + hi/lo planes (layer 1)
//      1 = BN+leaky -> hi/lo planes only       (layer 2)
//      2 = +bias upper half -> yl/yr fp32 64-wide (layer 3 transform)
// ===========================================================================
#define STRIDE 80
#define PSZ (128 * STRIDE)
#define BUFSZ (4 * PSZ)
#define OFF_MUL (2 * BUFSZ)
#define OFF_ADD (OFF_MUL + 128 * 4)
#define SMEM_PIPE (OFF_ADD + 128 * 4)

template <int NC, int EPI>
__global__ void __launch_bounds__(256)
gemm_pipe(const __nv_bfloat16* __restrict__ a0h, const __nv_bfloat16* __restrict__ a0l,
          const __nv_bfloat16* __restrict__ a1h, const __nv_bfloat16* __restrict__ a1l,
          const __nv_bfloat16* __restrict__ whi, const __nv_bfloat16* __restrict__ wlo,
          int wbase, const float* __restrict__ bias,
          const float* __restrict__ bng, const float* __restrict__ bnb,
          const float* __restrict__ bnm, const float* __restrict__ bnv,
          float* __restrict__ out, __nv_bfloat16* __restrict__ oh,
          __nv_bfloat16* __restrict__ ol, float* __restrict__ outr, int n) {
    extern __shared__ char smem[];
    const uint32_t sbase = smem_u32(smem);
    float* s_mul = (float*)(smem + OFF_MUL);
    float* s_add = (float*)(smem + OFF_ADD);

    const int tid = threadIdx.x;
    const int wid = tid >> 5;
    const int lane = tid & 31;
    const int row0 = blockIdx.x * 128;

    if (tid < 128) {
        if (EPI == 2) {
            s_add[tid] = (tid >= 64) ? bias[tid - 64] : 0.f;
        } else {
            float s = bng[tid] * rsqrtf(bnv[tid] + 1e-5f);
            s_mul[tid] = s;
            s_add[tid] = (bias[tid] - bnm[tid]) * s + bnb[tid];
        }
    }

    const int mrow0 = (wid & 3) * 32;
    const int ncol0 = (wid >> 2) * 64;

    const int sel = lane >> 3;
    const int lr8 = lane & 7;
    uint32_t aOff[2], bOff[4];
#pragma unroll
    for (int m = 0; m < 2; ++m)
        aOff[m] = (uint32_t)((mrow0 + m * 16 + (sel & 1) * 8 + lr8) * STRIDE +
                             (sel >> 1) * 16);
#pragma unroll
    for (int g = 0; g < 4; ++g)
        bOff[g] = (uint32_t)((ncol0 + g * 16 + (sel >> 1) * 8 + lr8) * STRIDE +
                             (sel & 1) * 16);

    auto load_chunk = [&](int buf, int ch) {
        const __nv_bfloat16* ah = (ch < 4) ? a0h : a1h;
        const __nv_bfloat16* al = (ch < 4) ? a0l : a1l;
        const int col0 = (ch & 3) * 32;
        const int wrow = wbase + ((ch < 4) ? 0 : 128);
        const uint32_t base = sbase + buf * BUFSZ;
#pragma unroll
        for (int i = 0; i < 2; ++i) {
            const int idx = tid + i * 256;
            const int r = idx >> 2;
            const uint32_t soff = (uint32_t)(r * STRIDE + (idx & 3) * 16);
            const int ge = col0 + (idx & 3) * 8;
            const size_t aoff = (size_t)(row0 + r) * 128 + ge;
            cp16(base + soff, ah + aoff);
            cp16(base + PSZ + soff, al + aoff);
            const size_t woff2 = (size_t)(wrow + r) * 128 + ge;
            cp16(base + 2 * PSZ + soff, whi + woff2);
            cp16(base + 3 * PSZ + soff, wlo + woff2);
        }
    };

    float acc[2][8][4];
#pragma unroll
    for (int m = 0; m < 2; ++m)
#pragma unroll
        for (int g = 0; g < 8; ++g)
#pragma unroll
            for (int q = 0; q < 4; ++q) acc[m][g][q] = 0.f;

    load_chunk(0, 0);
    cp_commit();

    for (int ch = 0; ch < NC; ++ch) {
        const int cur = ch & 1;
        cp_wait_all();
        __syncthreads();
        if (ch + 1 < NC) {
            load_chunk(cur ^ 1, ch + 1);
            cp_commit();
        }
        const uint32_t b0 = sbase + cur * BUFSZ;
#pragma unroll
        for (int kk = 0; kk < 2; ++kk) {
            const uint32_t kb = kk * 32;
            uint32_t ah[2][4], al[2][4];
            ldm_x4(ah[0], b0 + aOff[0] + kb);
            ldm_x4(al[0], b0 + PSZ + aOff[0] + kb);
            ldm_x4(ah[1], b0 + aOff[1] + kb);
            ldm_x4(al[1], b0 + PSZ + aOff[1] + kb);
#pragma unroll
            for (int g = 0; g < 4; ++g) {
                uint32_t bh[4], bl[4];
                ldm_x4(bh, b0 + 2 * PSZ + bOff[g] + kb);
                ldm_x4(bl, b0 + 3 * PSZ + bOff[g] + kb);
#pragma unroll
                for (int m = 0; m < 2; ++m) {
                    mma_bf16(acc[m][g * 2],     ah[m], bh);
                    mma_bf16(acc[m][g * 2],     al[m], bh);
                    mma_bf16(acc[m][g * 2],     ah[m], bl);
                    mma_bf16(acc[m][g * 2 + 1], ah[m], bh + 2);
                    mma_bf16(acc[m][g * 2 + 1], al[m], bh + 2);
                    mma_bf16(acc[m][g * 2 + 1], ah[m], bl + 2);
                }
            }
        }
        __syncthreads();
    }

    // ---- epilogue ----
    const int qrow = lane >> 2;
    const int qcol = (lane & 3) * 2;
#pragma unroll
    for (int m = 0; m < 2; ++m) {
        const int rA = row0 + mrow0 + m * 16 + qrow;
        const int rB = rA + 8;
#pragma unroll
        for (int g = 0; g < 8; ++g) {
            const int c0 = ncol0 + g * 8 + qcol;
            if (EPI == 2) {
                const bool is_yr = (c0 >= 64);
                float* outp = is_yr ? outr : out;
                const int cl = c0 - (is_yr ? 64 : 0);
                const float a0 = s_add[c0], a1 = s_add[c0 + 1];
                if (rA < n) {
                    float2 o;
                    o.x = acc[m][g][0] + a0;
                    o.y = acc[m][g][1] + a1;
                    *(float2*)(outp + (size_t)rA * 64 + cl) = o;
                }
                if (rB < n) {
                    float2 o;
                    o.x = acc[m][g][2] + a0;
                    o.y = acc[m][g][3] + a1;
                    *(float2*)(outp + (size_t)rB * 64 + cl) = o;
                }
            } else {
                const float m0 = s_mul[c0], m1 = s_mul[c0 + 1];
                const float a0 = s_add[c0], a1 = s_add[c0 + 1];
                if (rA < n) {
                    float f0 = acc[m][g][0] * m0 + a0;
                    float f1 = acc[m][g][1] * m1 + a1;
                    f0 = (f0 >= 0.f) ? f0 : 0.1f * f0;
                    f1 = (f1 >= 0.f) ? f1 : 0.1f * f1;
                    const size_t off = (size_t)rA * 128 + c0;
                    if (EPI == 0) {
                        float2 o; o.x = f0; o.y = f1;
                        *(float2*)(out + off) = o;
                    }
                    split2_store(oh, ol, off, f0, f1);
                }
                if (rB < n) {
                    float f2 = acc[m][g][2] * m0 + a0;
                    float f3 = acc[m][g][3] * m1 + a1;
                    f2 = (f2 >= 0.f) ? f2 : 0.1f * f2;
                    f3 = (f3 >= 0.f) ? f3 : 0.1f * f3;
                    const size_t off = (size_t)rB * 128 + c0;
                    if (EPI == 0) {
                        float2 o; o.x = f2; o.y = f3;
                        *(float2*)(out + off) = o;
                    }
                    split2_store(oh, ol, off, f2, f3);
                }
            }
        }
    }
}

// ===========================================================================
// gather+normalize (layer 3): out = l2norm(mean(w*yl3[src]) + yr3[node]), D=64
// ===========================================================================
__global__ void __launch_bounds__(256)
gather_fin(const float* __restrict__ yl, const float* __restrict__ yr,
           const int* __restrict__ rp, const int2* __restrict__ ep,
           float* __restrict__ out, int n) {
    const int node = (blockIdx.x * blockDim.x + threadIdx.x) >> 5;
    const int lane = threadIdx.x & 31;
    if (node >= n) return;

    const int s0 = rp[node];
    const int s1 = rp[node + 1];
    const float* xb = yl + lane * 2;

    float ax = 0.f, ay = 0.f;
    for (int base = s0; base < s1; base += 32) {
        const int m = min(32, s1 - base);
        int2 meta = make_int2(0, 0);
        if (lane < m) meta = ep[base + lane];
        int t = 0;
        for (; t + 4 <= m; t += 4) {
            const int   sA = __shfl_sync(0xffffffffu, meta.x, t);
            const float wA = __int_as_float(__shfl_sync(0xffffffffu, meta.y, t));
            const int   sB = __shfl_sync(0xffffffffu, meta.x, t + 1);
            const float wB = __int_as_float(__shfl_sync(0xffffffffu, meta.y, t + 1));
            const int   sC = __shfl_sync(0xffffffffu, meta.x, t + 2);
            const float wC = __int_as_float(__shfl_sync(0xffffffffu, meta.y, t + 2));
            const int   sD = __shfl_sync(0xffffffffu, meta.x, t + 3);
            const float wD = __int_as_float(__shfl_sync(0xffffffffu, meta.y, t + 3));
            const float2 vA = *(const float2*)(xb + (size_t)sA * 64);
            const float2 vB = *(const float2*)(xb + (size_t)sB * 64);
            const float2 vC = *(const float2*)(xb + (size_t)sC * 64);
            const float2 vD = *(const float2*)(xb + (size_t)sD * 64);
            ax += vA.x * wA + vB.x * wB + vC.x * wC + vD.x * wD;
            ay += vA.y * wA + vB.y * wB + vC.y * wC + vD.y * wD;
        }
        for (; t < m; ++t) {
            const int   sA = __shfl_sync(0xffffffffu, meta.x, t);
            const float wA = __int_as_float(__shfl_sync(0xffffffffu, meta.y, t));
            const float2 vA = *(const float2*)(xb + (size_t)sA * 64);
            ax += vA.x * wA; ay += vA.y * wA;
        }
    }
    const float inv = 1.0f / fmaxf((float)(s1 - s0), 1.0f);
    const float2 r = *(const float2*)(yr + (size_t)node * 64 + lane * 2);
    float v0 = ax * inv + r.x;
    float v1 = ay * inv + r.y;
    float ss = v0 * v0 + v1 * v1;
#pragma unroll
    for (int o = 16; o; o >>= 1) ss += __shfl_xor_sync(0xffffffffu, ss, o);
    const float sc = 1.0f / fmaxf(sqrtf(ss), 1e-12f);
    float2 o;
    o.x = v0 * sc; o.y = v1 * sc;
    *(float2*)(out + (size_t)node * 64 + lane * 2) = o;
}

// ===========================================================================
extern "C" void kernel_launch(void* const* d_in, const int* in_sizes, int n_in,
                              void* d_out, int out_size) {
    const float* x    = (const float*)d_in[0];
    const int*   ei   = (const int*)d_in[1];   // int32 (JAX canonicalizes int64)
    const float* ew   = (const float*)d_in[2];
    const float* W1l  = (const float*)d_in[3];
    const float* b1   = (const float*)d_in[4];
    const float* W1r  = (const float*)d_in[5];
    const float* W2l  = (const float*)d_in[6];
    const float* b2   = (const float*)d_in[7];
    const float* W2r  = (const float*)d_in[8];
    const float* W3l  = (const float*)d_in[9];
    const float* b3   = (const float*)d_in[10];
    const float* W3r  = (const float*)d_in[11];
    const float* bn1g = (const float*)d_in[12];
    const float* bn1b = (const float*)d_in[13];
    const float* bn1m = (const float*)d_in[14];
    const float* bn1v = (const float*)d_in[15];
    const float* bn2g = (const float*)d_in[16];
    const float* bn2b = (const float*)d_in[17];
    const float* bn2m = (const float*)d_in[18];
    const float* bn2v = (const float*)d_in[19];

    const int n = in_sizes[0] / NODES_D;
    const int e = in_sizes[2];

    float *h1, *yl3, *yr3;
    int *cnti, *rp, *rankp, *bsum;
    int2 *ep;
    __nv_bfloat16 *xsh, *xsl, *aggh, *aggl, *h1h, *h1l, *h2h, *h2l, *whi, *wlo;
    cudaGetSymbolAddress((void**)&h1, g_h1);
    cudaGetSymbolAddress((void**)&yl3, g_yl3);
    cudaGetSymbolAddress((void**)&yr3, g_yr3);
    cudaGetSymbolAddress((void**)&xsh, g_xs_hi);
    cudaGetSymbolAddress((void**)&xsl, g_xs_lo);
    cudaGetSymbolAddress((void**)&aggh, g_agg_hi);
    cudaGetSymbolAddress((void**)&aggl, g_agg_lo);
    cudaGetSymbolAddress((void**)&h1h, g_h1_hi);
    cudaGetSymbolAddress((void**)&h1l, g_h1_lo);
    cudaGetSymbolAddress((void**)&h2h, g_h2_hi);
    cudaGetSymbolAddress((void**)&h2l, g_h2_lo);
    cudaGetSymbolAddress((void**)&whi, g_whi);
    cudaGetSymbolAddress((void**)&wlo, g_wlo);
    cudaGetSymbolAddress((void**)&cnti, g_cnti);
    cudaGetSymbolAddress((void**)&rp, g_rp);
    cudaGetSymbolAddress((void**)&rankp, g_rank);
    cudaGetSymbolAddress((void**)&bsum, g_bsum);
    cudaGetSymbolAddress((void**)&ep, g_ep);

    cudaFuncSetAttribute(gemm_pipe<8, 0>,
                         cudaFuncAttributeMaxDynamicSharedMemorySize, SMEM_PIPE);
    cudaFuncSetAttribute(gemm_pipe<8, 1>,
                         cudaFuncAttributeMaxDynamicSharedMemorySize, SMEM_PIPE);
    cudaFuncSetAttribute(gemm_pipe<4, 2>,
                         cudaFuncAttributeMaxDynamicSharedMemorySize, SMEM_PIPE);

    const int* src = ei;
    const int* dst = ei + e;

    const int eb  = (e + 255) / 256;
    const int nbk = (n + 255) / 256;
    const int nb1024 = (n + 1023) / 1024;
    const int spb = ((WROWS + n) * 32 + 255) / 256;
    const int gbk = (n + 7) / 8;            // gather: 8 warps/block
    const int gb  = (n + 127) / 128;        // gemm: 128 rows/block

    // ---- prep (splits + degree count) + CSR ----
    cudaMemsetAsync(cnti, 0, (size_t)n * sizeof(int), 0);
    prep_k<<<spb + eb, 256>>>(W1l, W1r, W2l, W2r, W3l, W3r, x,
                              whi, wlo, xsh, xsl, dst, cnti, rankp, n, e, spb);
    scan1_k<<<nb1024, 256>>>(cnti, rp, bsum, n);
    scan3m_k<<<nbk, 256>>>(rp, bsum, n, e, nb1024);
    fill_k<<<eb, 256>>>(src, dst, ew, rp, rankp, ep, e);

    // ---- Layer 1 ----
    gather_sp<<<gbk, 256>>>(x, rp, ep, aggh, aggl, n);
    gemm_pipe<8, 0><<<gb, 256, SMEM_PIPE>>>(aggh, aggl, xsh, xsl, whi, wlo, 0,
                                            b1, bn1g, bn1b, bn1m, bn1v,
                                            h1, h1h, h1l, nullptr, n);
    // ---- Layer 2 ----
    gather_sp<<<gbk, 256>>>(h1, rp, ep, aggh, aggl, n);
    gemm_pipe<8, 1><<<gb, 256, SMEM_PIPE>>>(aggh, aggl, h1h, h1l, whi, wlo, 256,
                                            b2, bn2g, bn2b, bn2m, bn2v,
                                            nullptr, h2h, h2l, nullptr, n);
    // ---- Layer 3 (transform-first + L2 normalize) ----
    gemm_pipe<4, 2><<<gb, 256, SMEM_PIPE>>>(h2h, h2l, nullptr, nullptr, whi, wlo, 512,
                                            b3, nullptr, nullptr, nullptr, nullptr,
                                            yl3, nullptr, nullptr, yr3, n);
    gather_fin<<<gbk, 256>>>(yl3, yr3, rp, ep, (float*)d_out, n);
}